// round 3
// baseline (speedup 1.0000x reference)
#include <cuda_runtime.h>
#include <cuda_bf16.h>
#include <cstdint>

// ---------------------------------------------------------------------------
// STDP delta_w on GB300 — base-sm_103-legal tensor core path (mma.sync bf16).
// (tcgen05/TMEM is rejected: harness assembles PTX for sm_103, not sm_103a.)
//
//   trace_t = 0.5*trace_{t-1} + in_t
//   dw[o,i] = sum_{t,b} trace[t,b,i] * out[t,b,o]
//
// Grid: 32 time-chunks x 4 batch-slices = 128 CTAs, 512 threads.
// Per CTA/step: fp32 trace in regs -> bf16 swizzled smem tiles ->
// ldmatrix.x4.trans -> mma.sync m16n8k16 (fp32 acc in regs) ->
// epilogue red.global.add.v2.f32.
// ---------------------------------------------------------------------------

#define T_STEPS 2048
#define B_DIM   128
#define N_IN    256
#define N_OUT   128
#define CHUNK   64
#define GT      (T_STEPS / CHUNK)   // 32
#define KB      32
#define NBS     (B_DIM / KB)        // 4
#define WARMUP  16                  // 0.5^16 ~ 1.5e-5 truncation
#define NTHR    512

// Static smem: trace tile [KB=32][256] bf16 (512B rows), out tile [32][128] bf16 (256B rows)
#define TR_OFF   0
#define OT_OFF   16384
#define SM_TOTAL 24576

__device__ __forceinline__ uint32_t smem_u32(const void* p) {
    uint32_t a;
    asm("{ .reg .u64 t; cvta.to.shared.u64 t, %1; cvt.u32.u64 %0, t; }" : "=r"(a) : "l"(p));
    return a;
}

__device__ __forceinline__ void ldsm4t(uint32_t* d, uint32_t a) {
    asm volatile("ldmatrix.sync.aligned.m8n8.x4.trans.shared.b16 {%0,%1,%2,%3}, [%4];"
                 : "=r"(d[0]), "=r"(d[1]), "=r"(d[2]), "=r"(d[3]) : "r"(a));
}

__device__ __forceinline__ void mma16816(float* d, const uint32_t* a, const uint32_t* b) {
    asm volatile(
        "mma.sync.aligned.m16n8k16.row.col.f32.bf16.bf16.f32 "
        "{%0,%1,%2,%3},{%4,%5,%6,%7},{%8,%9},{%0,%1,%2,%3};"
        : "+f"(d[0]), "+f"(d[1]), "+f"(d[2]), "+f"(d[3])
        : "r"(a[0]), "r"(a[1]), "r"(a[2]), "r"(a[3]), "r"(b[0]), "r"(b[1]));
}

__device__ __forceinline__ uint32_t pack_bf16x2(float x, float y) {
    __nv_bfloat162 h = __float22bfloat162_rn(make_float2(x, y));
    return *reinterpret_cast<uint32_t*>(&h);
}

__global__ void stdp_zero_kernel(float* __restrict__ p, int n) {
    int i = blockIdx.x * blockDim.x + threadIdx.x;
    if (i < n) p[i] = 0.0f;
}

__global__ void __launch_bounds__(NTHR, 1)
stdp_main_kernel(const float* __restrict__ gin,   // [T, B, N_IN]
                 const float* __restrict__ gout,  // [T, B, N_OUT]
                 float* __restrict__ dw)          // [N_OUT, N_IN]
{
    __shared__ __align__(1024) char smem[SM_TOTAL];
    const uint32_t sb = smem_u32(smem);
    const int tid = threadIdx.x;
    const int w   = tid >> 5;
    const int l   = tid & 31;

    const int t0 = blockIdx.x * CHUNK;
    const int b0 = blockIdx.y * KB;

    // ---- per-thread global float4 offsets + smem store offsets --------------
    // in tile:  [32 b][256 i] -> 2048 float4; f = tid + 512q, q<4
    //           b = f>>6, i = (f&63)*4
    // out tile: [32 b][128 o] -> 1024 float4; f = tid + 512q, q<2
    //           b = f>>5, o = (f&31)*4
    int off4_in[4];  uint32_t sts_in[4];
#pragma unroll
    for (int q = 0; q < 4; q++) {
        int f  = tid + 512 * q;
        int bl = f >> 6;
        int i4 = (f & 63) << 2;
        off4_in[q] = (b0 + bl) * (N_IN / 4) + (f & 63);
        sts_in[q]  = (uint32_t)(TR_OFF + bl * 512 +
                                (((i4 >> 3) ^ (bl & 7)) << 4) + ((i4 & 7) << 1));
    }
    int off4_out[2]; uint32_t sts_out[2];
#pragma unroll
    for (int q = 0; q < 2; q++) {
        int f  = tid + 512 * q;
        int bl = f >> 5;
        int o4 = (f & 31) << 2;
        off4_out[q] = (b0 + bl) * (N_OUT / 4) + (f & 31);
        sts_out[q]  = (uint32_t)(OT_OFF + bl * 256 +
                                 (((o4 >> 3) ^ (bl & 7)) << 4) + ((o4 & 7) << 1));
    }

    // ---- ldmatrix source addresses ------------------------------------------
    // Warp tile: o in [wr*32, +32), i in [wc*64, +64)
    const int wr = w >> 2, wc = w & 3;
    const int obase = wr * 32, ibase = wc * 64;

    // A (out tile, trans): x4 quadrant order (m0-7,k0-7)(m8-15,k0-7)(m0-7,k8-15)(m8-15,k8-15)
    // stored as O[b][o]: lanes 0-7/8-15 rows b0-7 (chunks o, o+8), lanes16-31 rows b8-15.
    uint32_t a_addr[2];
#pragma unroll
    for (int mt = 0; mt < 2; mt++) {
        int b  = (l & 7) + ((l >> 4) << 3);
        int ch = ((obase + mt * 16) >> 3) + ((l >> 3) & 1);
        a_addr[mt] = sb + OT_OFF + b * 256 + ((ch ^ (b & 7)) << 4);
    }
    // B (trace tile, trans): quadrants (k0-7,i0-7)(k8-15,i0-7)(k0-7,i8-15)(k8-15,i8-15)
    uint32_t b_addr[4];
#pragma unroll
    for (int np = 0; np < 4; np++) {
        int b  = (l & 7) + (((l >> 3) & 1) << 3);
        int ch = ((ibase + np * 16) >> 3) + ((l >> 4) & 1);
        b_addr[np] = sb + TR_OFF + b * 512 + ((ch ^ (b & 7)) << 4);
    }

    // ---- trace warm-up ------------------------------------------------------
    float4 tr4[4];
#pragma unroll
    for (int q = 0; q < 4; q++) tr4[q] = make_float4(0.f, 0.f, 0.f, 0.f);

    int tw0 = t0 - WARMUP; if (tw0 < 0) tw0 = 0;
    for (int t = tw0; t < t0; t++) {
        const float4* pin = reinterpret_cast<const float4*>(gin) + (size_t)t * (B_DIM * N_IN / 4);
#pragma unroll
        for (int q = 0; q < 4; q++) {
            float4 v = pin[off4_in[q]];
            tr4[q].x = fmaf(0.5f, tr4[q].x, v.x);
            tr4[q].y = fmaf(0.5f, tr4[q].y, v.y);
            tr4[q].z = fmaf(0.5f, tr4[q].z, v.z);
            tr4[q].w = fmaf(0.5f, tr4[q].w, v.w);
        }
    }

    float acc[2][8][4];
#pragma unroll
    for (int mt = 0; mt < 2; mt++)
#pragma unroll
        for (int nt = 0; nt < 8; nt++)
#pragma unroll
            for (int r = 0; r < 4; r++) acc[mt][nt][r] = 0.0f;

    // ---- preload step 0 -----------------------------------------------------
    float4 vin[4], vout[2];
    {
        const float4* pin  = reinterpret_cast<const float4*>(gin)  + (size_t)t0 * (B_DIM * N_IN  / 4);
        const float4* pout = reinterpret_cast<const float4*>(gout) + (size_t)t0 * (B_DIM * N_OUT / 4);
#pragma unroll
        for (int q = 0; q < 4; q++) vin[q]  = pin[off4_in[q]];
#pragma unroll
        for (int q = 0; q < 2; q++) vout[q] = pout[off4_out[q]];
    }

    // ---- main loop ----------------------------------------------------------
    for (int s = 0; s < CHUNK; s++) {
        // trace update + bf16 convert + swizzled STS
#pragma unroll
        for (int q = 0; q < 4; q++) {
            tr4[q].x = fmaf(0.5f, tr4[q].x, vin[q].x);
            tr4[q].y = fmaf(0.5f, tr4[q].y, vin[q].y);
            tr4[q].z = fmaf(0.5f, tr4[q].z, vin[q].z);
            tr4[q].w = fmaf(0.5f, tr4[q].w, vin[q].w);
            uint2 u = make_uint2(pack_bf16x2(tr4[q].x, tr4[q].y),
                                 pack_bf16x2(tr4[q].z, tr4[q].w));
            *reinterpret_cast<uint2*>(smem + sts_in[q]) = u;
        }
#pragma unroll
        for (int q = 0; q < 2; q++) {
            uint2 u = make_uint2(pack_bf16x2(vout[q].x, vout[q].y),
                                 pack_bf16x2(vout[q].z, vout[q].w));
            *reinterpret_cast<uint2*>(smem + sts_out[q]) = u;
        }

        // prefetch next step (latency hides under barrier + MMA phase)
        if (s + 1 < CHUNK) {
            const int t = t0 + s + 1;
            const float4* pin  = reinterpret_cast<const float4*>(gin)  + (size_t)t * (B_DIM * N_IN  / 4);
            const float4* pout = reinterpret_cast<const float4*>(gout) + (size_t)t * (B_DIM * N_OUT / 4);
#pragma unroll
            for (int q = 0; q < 4; q++) vin[q]  = pin[off4_in[q]];
#pragma unroll
            for (int q = 0; q < 2; q++) vout[q] = pout[off4_out[q]];
        }

        __syncthreads();

        // MMA phase: K = 32 (two k16 blocks)
#pragma unroll
        for (int kb = 0; kb < 2; kb++) {
            uint32_t af[2][4];
            ldsm4t(af[0], a_addr[0] + kb * 16 * 256);
            ldsm4t(af[1], a_addr[1] + kb * 16 * 256);
#pragma unroll
            for (int np = 0; np < 4; np++) {
                uint32_t bf[4];
                ldsm4t(bf, b_addr[np] + kb * 16 * 512);
#pragma unroll
                for (int mt = 0; mt < 2; mt++) {
                    mma16816(acc[mt][2 * np],     af[mt], bf);
                    mma16816(acc[mt][2 * np + 1], af[mt], bf + 2);
                }
            }
        }

        __syncthreads();
    }

    // ---- epilogue: vector reductions into dw --------------------------------
#pragma unroll
    for (int mt = 0; mt < 2; mt++) {
#pragma unroll
        for (int nt = 0; nt < 8; nt++) {
            const int o = obase + mt * 16 + (l >> 2);
            const int i = ibase + nt * 8 + ((l & 3) << 1);
            float* p = dw + (size_t)o * N_IN + i;
            asm volatile("red.global.add.v2.f32 [%0], {%1,%2};"
                         :: "l"(p), "f"(acc[mt][nt][0]), "f"(acc[mt][nt][1]) : "memory");
            asm volatile("red.global.add.v2.f32 [%0], {%1,%2};"
                         :: "l"(p + 8 * N_IN), "f"(acc[mt][nt][2]), "f"(acc[mt][nt][3]) : "memory");
        }
    }
}

extern "C" void kernel_launch(void* const* d_in, const int* in_sizes, int n_in,
                              void* d_out, int out_size) {
    (void)in_sizes; (void)n_in; (void)out_size;
    const float* gin  = (const float*)d_in[0];   // in_spikes  [T, B, N_IN]
    const float* gout = (const float*)d_in[1];   // out_spikes [T, B, N_OUT]
    float* dw = (float*)d_out;                   // [N_OUT, N_IN]

    stdp_zero_kernel<<<(N_OUT * N_IN + NTHR - 1) / NTHR, NTHR>>>(dw, N_OUT * N_IN);

    dim3 grid(GT, NBS);
    stdp_main_kernel<<<grid, NTHR>>>(gin, gout, dw);
}

// round 4
// speedup vs baseline: 1.5972x; 1.5972x over previous
#include <cuda_runtime.h>
#include <cuda_bf16.h>
#include <cstdint>

// ---------------------------------------------------------------------------
// STDP delta_w on GB300 — base-sm_103-legal tensor core path (mma.sync bf16).
//
//   trace_t = 0.5*trace_{t-1} + in_t
//   dw[o,i] = sum_{t,b} trace[t,b,i] * out[t,b,o]
//
// R3: latency-bound fix. cp.async 2-deep fp32 staging for `in` (self-consumed
// slots -> no barrier needed for staging), double-buffered bf16 MMA tiles ->
// a single __syncthreads per timestep, `out` via distance-1 register prefetch.
// ---------------------------------------------------------------------------

#define T_STEPS 2048
#define B_DIM   128
#define N_IN    256
#define N_OUT   128
#define CHUNK   64
#define GT      (T_STEPS / CHUNK)   // 32
#define KB      32
#define NBS     (B_DIM / KB)        // 4
#define WARMUP  16                  // 0.5^16 ~ 1.5e-5 truncation
#define NTHR    512

// Dynamic smem layout (bytes):
//   [0, 65536)        fp32 `in` staging, 2 bufs x 32KB, slot f*16 (f = tid+512q)
//   [65536, 98304)    trace bf16 tile, 2 bufs x 16KB (32 rows x 512B, swizzled)
//   [98304, 114688)   out   bf16 tile, 2 bufs x  8KB (32 rows x 256B, swizzled)
#define SI_OFF   0
#define SI_BSZ   32768
#define TR_OFF   65536
#define TR_BSZ   16384
#define OT_OFF   98304
#define OT_BSZ   8192
#define SM_TOTAL 114688

__device__ __forceinline__ uint32_t smem_u32(const void* p) {
    uint32_t a;
    asm("{ .reg .u64 t; cvta.to.shared.u64 t, %1; cvt.u32.u64 %0, t; }" : "=r"(a) : "l"(p));
    return a;
}

__device__ __forceinline__ void cp16(uint32_t s, const void* g) {
    asm volatile("cp.async.cg.shared.global [%0], [%1], 16;" :: "r"(s), "l"(g) : "memory");
}
#define CP_COMMIT() asm volatile("cp.async.commit_group;" ::: "memory")
#define CP_WAIT1()  asm volatile("cp.async.wait_group 1;" ::: "memory")

__device__ __forceinline__ void ldsm4t(uint32_t* d, uint32_t a) {
    asm volatile("ldmatrix.sync.aligned.m8n8.x4.trans.shared.b16 {%0,%1,%2,%3}, [%4];"
                 : "=r"(d[0]), "=r"(d[1]), "=r"(d[2]), "=r"(d[3]) : "r"(a));
}

__device__ __forceinline__ void mma16816(float* d, const uint32_t* a, const uint32_t* b) {
    asm volatile(
        "mma.sync.aligned.m16n8k16.row.col.f32.bf16.bf16.f32 "
        "{%0,%1,%2,%3},{%4,%5,%6,%7},{%8,%9},{%0,%1,%2,%3};"
        : "+f"(d[0]), "+f"(d[1]), "+f"(d[2]), "+f"(d[3])
        : "r"(a[0]), "r"(a[1]), "r"(a[2]), "r"(a[3]), "r"(b[0]), "r"(b[1]));
}

__device__ __forceinline__ uint32_t pack_bf16x2(float x, float y) {
    __nv_bfloat162 h = __float22bfloat162_rn(make_float2(x, y));
    return *reinterpret_cast<uint32_t*>(&h);
}

__global__ void stdp_zero_kernel(float* __restrict__ p, int n) {
    int i = blockIdx.x * blockDim.x + threadIdx.x;
    if (i < n) p[i] = 0.0f;
}

__global__ void __launch_bounds__(NTHR, 1)
stdp_main_kernel(const float* __restrict__ gin,   // [T, B, N_IN]
                 const float* __restrict__ gout,  // [T, B, N_OUT]
                 float* __restrict__ dw)          // [N_OUT, N_IN]
{
    extern __shared__ __align__(1024) char smem[];
    const uint32_t sb = smem_u32(smem);
    const int tid = threadIdx.x;
    const int w   = tid >> 5;
    const int l   = tid & 31;

    const int t0 = blockIdx.x * CHUNK;
    const int b0 = blockIdx.y * KB;

    // ---- per-thread offsets -------------------------------------------------
    // in tile:  f = tid + 512q, q<4;  b = f>>6, i = (f&63)*4
    // out tile: f = tid + 512q, q<2;  b = f>>5, o = (f&31)*4
    int gi_off[4];          // byte offset within one timestep's in slab
    uint32_t si_slot[4];    // staging slot (relative)
    uint32_t sts_in[4];     // swizzled bf16 STS offset (relative to TR buf)
#pragma unroll
    for (int q = 0; q < 4; q++) {
        int f  = tid + 512 * q;
        int bl = f >> 6;
        int i4 = (f & 63) << 2;
        gi_off[q]  = ((b0 + bl) * (N_IN / 4) + (f & 63)) * 16;
        si_slot[q] = (uint32_t)(f * 16);
        sts_in[q]  = (uint32_t)(bl * 512 + (((i4 >> 3) ^ (bl & 7)) << 4) + ((i4 & 7) << 1));
    }
    int go_off[2]; uint32_t sts_out[2];
#pragma unroll
    for (int q = 0; q < 2; q++) {
        int f  = tid + 512 * q;
        int bl = f >> 5;
        int o4 = (f & 31) << 2;
        go_off[q]  = (b0 + bl) * (N_OUT / 4) + (f & 31);
        sts_out[q] = (uint32_t)(bl * 256 + (((o4 >> 3) ^ (bl & 7)) << 4) + ((o4 & 7) << 1));
    }

    // ---- ldmatrix source addresses (relative to buf base) -------------------
    const int wr = w >> 2, wc = w & 3;
    const int obase = wr * 32, ibase = wc * 64;

    uint32_t a_addr[2];
#pragma unroll
    for (int mt = 0; mt < 2; mt++) {
        int b  = (l & 7) + ((l >> 4) << 3);
        int ch = ((obase + mt * 16) >> 3) + ((l >> 3) & 1);
        a_addr[mt] = (uint32_t)(b * 256 + ((ch ^ (b & 7)) << 4));
    }
    uint32_t b_addr[4];
#pragma unroll
    for (int np = 0; np < 4; np++) {
        int b  = (l & 7) + (((l >> 3) & 1) << 3);
        int ch = ((ibase + np * 16) >> 3) + ((l >> 4) & 1);
        b_addr[np] = (uint32_t)(b * 512 + ((ch ^ (b & 7)) << 4));
    }

    // ---- stage steps t0, t0+1 via cp.async (overlaps warm-up below) ---------
#pragma unroll
    for (int p = 0; p < 2; p++) {
        const char* src = (const char*)gin + (size_t)(t0 + p) * (B_DIM * N_IN * 4);
#pragma unroll
        for (int q = 0; q < 4; q++)
            cp16(sb + SI_OFF + p * SI_BSZ + si_slot[q], src + gi_off[q]);
        CP_COMMIT();
    }

    // ---- trace warm-up ------------------------------------------------------
    float4 tr4[4];
#pragma unroll
    for (int q = 0; q < 4; q++) tr4[q] = make_float4(0.f, 0.f, 0.f, 0.f);

    int tw0 = t0 - WARMUP; if (tw0 < 0) tw0 = 0;
#pragma unroll 2
    for (int t = tw0; t < t0; t++) {
        const char* src = (const char*)gin + (size_t)t * (B_DIM * N_IN * 4);
#pragma unroll
        for (int q = 0; q < 4; q++) {
            float4 v = *reinterpret_cast<const float4*>(src + gi_off[q]);
            tr4[q].x = fmaf(0.5f, tr4[q].x, v.x);
            tr4[q].y = fmaf(0.5f, tr4[q].y, v.y);
            tr4[q].z = fmaf(0.5f, tr4[q].z, v.z);
            tr4[q].w = fmaf(0.5f, tr4[q].w, v.w);
        }
    }

    float acc[2][8][4];
#pragma unroll
    for (int mt = 0; mt < 2; mt++)
#pragma unroll
        for (int nt = 0; nt < 8; nt++)
#pragma unroll
            for (int r = 0; r < 4; r++) acc[mt][nt][r] = 0.0f;

    // out: distance-1 register prefetch
    float4 vout[2];
    {
        const float4* po = reinterpret_cast<const float4*>(gout) + (size_t)t0 * (B_DIM * N_OUT / 4);
#pragma unroll
        for (int q = 0; q < 2; q++) vout[q] = po[go_off[q]];
    }

    // ---- main loop: ONE barrier per timestep --------------------------------
    for (int s = 0; s < CHUNK; s++) {
        const uint32_t buf = s & 1;
        const uint32_t si_base = sb + SI_OFF + buf * SI_BSZ;
        const uint32_t tr_base_rel = TR_OFF + buf * TR_BSZ;
        const uint32_t ot_base_rel = OT_OFF + buf * OT_BSZ;

        CP_WAIT1();   // step s's `in` staging complete (self-filled slots)

        // trace update from staged fp32, convert, swizzled STS (bf16)
#pragma unroll
        for (int q = 0; q < 4; q++) {
            float4 v = *reinterpret_cast<const float4*>(smem + buf * SI_BSZ + si_slot[q]);
            tr4[q].x = fmaf(0.5f, tr4[q].x, v.x);
            tr4[q].y = fmaf(0.5f, tr4[q].y, v.y);
            tr4[q].z = fmaf(0.5f, tr4[q].z, v.z);
            tr4[q].w = fmaf(0.5f, tr4[q].w, v.w);
            uint2 u = make_uint2(pack_bf16x2(tr4[q].x, tr4[q].y),
                                 pack_bf16x2(tr4[q].z, tr4[q].w));
            *reinterpret_cast<uint2*>(smem + tr_base_rel + sts_in[q]) = u;
        }
#pragma unroll
        for (int q = 0; q < 2; q++) {
            uint2 u = make_uint2(pack_bf16x2(vout[q].x, vout[q].y),
                                 pack_bf16x2(vout[q].z, vout[q].w));
            *reinterpret_cast<uint2*>(smem + ot_base_rel + sts_out[q]) = u;
        }

        // refill staging buffer with step s+2 (slots already consumed above)
        if (s + 2 < CHUNK) {
            const char* src = (const char*)gin + (size_t)(t0 + s + 2) * (B_DIM * N_IN * 4);
#pragma unroll
            for (int q = 0; q < 4; q++) cp16(si_base + si_slot[q], src + gi_off[q]);
        }
        CP_COMMIT();  // unconditional: keeps group accounting uniform

        // prefetch out step s+1
        if (s + 1 < CHUNK) {
            const float4* po = reinterpret_cast<const float4*>(gout)
                             + (size_t)(t0 + s + 1) * (B_DIM * N_OUT / 4);
#pragma unroll
            for (int q = 0; q < 2; q++) vout[q] = po[go_off[q]];
        }

        __syncthreads();

        // MMA phase: K = 32 (two k16 blocks)
        const uint32_t abase = sb + ot_base_rel;
        const uint32_t bbase = sb + tr_base_rel;
#pragma unroll
        for (int kb = 0; kb < 2; kb++) {
            uint32_t af[2][4];
            ldsm4t(af[0], abase + a_addr[0] + kb * 16 * 256);
            ldsm4t(af[1], abase + a_addr[1] + kb * 16 * 256);
#pragma unroll
            for (int np = 0; np < 4; np++) {
                uint32_t bf[4];
                ldsm4t(bf, bbase + b_addr[np] + kb * 16 * 512);
#pragma unroll
                for (int mt = 0; mt < 2; mt++) {
                    mma16816(acc[mt][2 * np],     af[mt], bf);
                    mma16816(acc[mt][2 * np + 1], af[mt], bf + 2);
                }
            }
        }
        // no second barrier: next iter writes the OTHER tile buffer
    }

    // ---- epilogue: vector reductions into dw --------------------------------
#pragma unroll
    for (int mt = 0; mt < 2; mt++) {
#pragma unroll
        for (int nt = 0; nt < 8; nt++) {
            const int o = obase + mt * 16 + (l >> 2);
            const int i = ibase + nt * 8 + ((l & 3) << 1);
            float* p = dw + (size_t)o * N_IN + i;
            asm volatile("red.global.add.v2.f32 [%0], {%1,%2};"
                         :: "l"(p), "f"(acc[mt][nt][0]), "f"(acc[mt][nt][1]) : "memory");
            asm volatile("red.global.add.v2.f32 [%0], {%1,%2};"
                         :: "l"(p + 8 * N_IN), "f"(acc[mt][nt][2]), "f"(acc[mt][nt][3]) : "memory");
        }
    }
}

extern "C" void kernel_launch(void* const* d_in, const int* in_sizes, int n_in,
                              void* d_out, int out_size) {
    (void)in_sizes; (void)n_in; (void)out_size;
    const float* gin  = (const float*)d_in[0];   // in_spikes  [T, B, N_IN]
    const float* gout = (const float*)d_in[1];   // out_spikes [T, B, N_OUT]
    float* dw = (float*)d_out;                   // [N_OUT, N_IN]

    stdp_zero_kernel<<<(N_OUT * N_IN + NTHR - 1) / NTHR, NTHR>>>(dw, N_OUT * N_IN);

    cudaFuncSetAttribute(stdp_main_kernel,
                         cudaFuncAttributeMaxDynamicSharedMemorySize, SM_TOTAL);
    dim3 grid(GT, NBS);
    stdp_main_kernel<<<grid, NTHR, SM_TOTAL>>>(gin, gout, dw);
}